// round 1
// baseline (speedup 1.0000x reference)
#include <cuda_runtime.h>

#define N 4096
#define NN (N*N)
#define NF 4
#define MORD 32
#define NC (MORD+1)

#define BM 128
#define BN 128
#define BK 16
#define TM 8
#define TN 8

// Scratch: three ping-pong Chebyshev-term buffers (T_{k-2}, T_{k-1}, T_k).
__device__ float g_T0[NN];
__device__ float g_T1[NN];
__device__ float g_T2[NN];
__device__ float g_coef[NC * NF];   // 64 * (o==0 ? 0.5 : 1) * c[o][f]

__device__ __forceinline__ float* t_buf(int i) {
    return (i == 0) ? g_T0 : ((i == 1) ? g_T1 : g_T2);
}

// ---------------------------------------------------------------------------
// Chebyshev coefficients of the heat-kernel bank, computed in fp64.
// c[o][f] = (2/Nc) * sum_j cos(pi*o*(j+.5)/Nc) * exp(-tau_f*(cos(pi*(j+.5)/Nc)+1))
// Folded in: sqrt(N)=64 global scale and the 0.5 factor on order 0.
// ---------------------------------------------------------------------------
__global__ void coef_kernel() {
    int t = threadIdx.x;
    if (t >= NC * NF) return;
    int o = t >> 2;
    int f = t & 3;
    const double taus[4] = {0.5, 1.0, 2.0, 4.0};
    const double PI = 3.14159265358979323846;
    double s = 0.0;
    for (int j = 0; j < NC; j++) {
        double u = (j + 0.5) / (double)NC;
        double x = cos(PI * u) + 1.0;           // a1*cos + a2 with a1=a2=1
        s += cos(PI * (double)o * u) * exp(-taus[f] * x);
    }
    double c = (2.0 / (double)NC) * s * 64.0;   // sqrt(4096) = 64
    if (o == 0) c *= 0.5;
    g_coef[o * NF + f] = (float)c;
}

// ---------------------------------------------------------------------------
// Init: T0 = I, T1 = L - I, out[f] = coef[0][f]*I + coef[1][f]*T1
// ---------------------------------------------------------------------------
__global__ void init_kernel(const float* __restrict__ L, float* __restrict__ out) {
    int idx = blockIdx.x * blockDim.x + threadIdx.x;
    if (idx >= NN) return;
    int i = idx >> 12;
    int j = idx & (N - 1);
    float l = L[idx];
    float diag = (i == j) ? 1.0f : 0.0f;
    float t1 = l - diag;
    g_T0[idx] = diag;
    g_T1[idx] = t1;
#pragma unroll
    for (int f = 0; f < NF; f++)
        out[f * NN + idx] = g_coef[0 * NF + f] * diag + g_coef[1 * NF + f] * t1;
}

// ---------------------------------------------------------------------------
// One Chebyshev step, fully fused:
//   Tnew = 2*(L @ Tcur) - 2*Tcur - Told        (since factor = 2*(L - I))
//   out[f] += coef[k][f] * Tnew  for f = 0..3
// Classic 128x128x16 double-buffered SGEMM, 256 threads, 8x8 microtile.
// ---------------------------------------------------------------------------
__global__ void __launch_bounds__(256, 2)
cheb_step_kernel(const float* __restrict__ L, float* __restrict__ out,
                 int rot, int kidx)
{
    const float* __restrict__ Told = t_buf(rot);
    const float* __restrict__ Tcur = t_buf((rot + 1) % 3);
    float* __restrict__ Tnew = t_buf((rot + 2) % 3);

    __shared__ __align__(16) float As[2][BK][BM + 4];  // transposed A tile
    __shared__ __align__(16) float Bs[2][BK][BN];

    const int tid = threadIdx.x;
    const int tx = tid & 15;          // 16 threads across N
    const int ty = tid >> 4;          // 16 threads across M
    const int i0 = blockIdx.y * BM;
    const int j0 = blockIdx.x * BN;

    // A-tile load mapping: 512 float4 (128 rows x 4 float4/row), 2 per thread
    const int av0 = tid, av1 = tid + 256;
    const int ar0 = av0 >> 2, ac0 = (av0 & 3) * 4;
    const int ar1 = av1 >> 2, ac1 = (av1 & 3) * 4;
    // B-tile load mapping: 512 float4 (16 rows x 32 float4/row), 2 per thread
    const int br0 = av0 >> 5, bc0 = (av0 & 31) * 4;
    const int br1 = av1 >> 5, bc1 = (av1 & 31) * 4;

    float acc[TM][TN];
#pragma unroll
    for (int r = 0; r < TM; r++)
#pragma unroll
        for (int c = 0; c < TN; c++) acc[r][c] = 0.0f;

    const int NT = N / BK;

    // Prologue: stage tile 0
    {
        float4 a0 = *(const float4*)&L[(i0 + ar0) * N + 0 * BK + ac0];
        float4 a1 = *(const float4*)&L[(i0 + ar1) * N + 0 * BK + ac1];
        float4 b0 = *(const float4*)&Tcur[(0 * BK + br0) * N + j0 + bc0];
        float4 b1 = *(const float4*)&Tcur[(0 * BK + br1) * N + j0 + bc1];
        As[0][ac0 + 0][ar0] = a0.x; As[0][ac0 + 1][ar0] = a0.y;
        As[0][ac0 + 2][ar0] = a0.z; As[0][ac0 + 3][ar0] = a0.w;
        As[0][ac1 + 0][ar1] = a1.x; As[0][ac1 + 1][ar1] = a1.y;
        As[0][ac1 + 2][ar1] = a1.z; As[0][ac1 + 3][ar1] = a1.w;
        *(float4*)&Bs[0][br0][bc0] = b0;
        *(float4*)&Bs[0][br1][bc1] = b1;
    }
    __syncthreads();

    for (int t = 0; t < NT; t++) {
        const int buf = t & 1;
        float4 na0, na1, nb0, nb1;
        const bool more = (t + 1 < NT);
        if (more) {
            const int kk = (t + 1) * BK;
            na0 = *(const float4*)&L[(i0 + ar0) * N + kk + ac0];
            na1 = *(const float4*)&L[(i0 + ar1) * N + kk + ac1];
            nb0 = *(const float4*)&Tcur[(kk + br0) * N + j0 + bc0];
            nb1 = *(const float4*)&Tcur[(kk + br1) * N + j0 + bc1];
        }

#pragma unroll
        for (int kk = 0; kk < BK; kk++) {
            float a[TM], b[TN];
#pragma unroll
            for (int r = 0; r < TM; r++) a[r] = As[buf][kk][ty * TM + r];
#pragma unroll
            for (int c = 0; c < TN; c++) b[c] = Bs[buf][kk][tx * TN + c];
#pragma unroll
            for (int r = 0; r < TM; r++)
#pragma unroll
                for (int c = 0; c < TN; c++) acc[r][c] = fmaf(a[r], b[c], acc[r][c]);
        }

        if (more) {
            const int nb = buf ^ 1;
            As[nb][ac0 + 0][ar0] = na0.x; As[nb][ac0 + 1][ar0] = na0.y;
            As[nb][ac0 + 2][ar0] = na0.z; As[nb][ac0 + 3][ar0] = na0.w;
            As[nb][ac1 + 0][ar1] = na1.x; As[nb][ac1 + 1][ar1] = na1.y;
            As[nb][ac1 + 2][ar1] = na1.z; As[nb][ac1 + 3][ar1] = na1.w;
            *(float4*)&Bs[nb][br0][bc0] = nb0;
            *(float4*)&Bs[nb][br1][bc1] = nb1;
        }
        __syncthreads();
    }

    // Fused epilogue: Tnew = 2*acc - 2*Tcur - Told ; out[f] += coef*Tnew
    float cf[NF];
#pragma unroll
    for (int f = 0; f < NF; f++) cf[f] = g_coef[kidx * NF + f];

#pragma unroll
    for (int r = 0; r < TM; r++) {
        const int gi = i0 + ty * TM + r;
        const int base = gi * N + j0 + tx * TN;
#pragma unroll
        for (int h = 0; h < 2; h++) {   // two float4 per 8-wide row
            const int b4 = base + h * 4;
            float4 tc = *(const float4*)&Tcur[b4];
            float4 to = *(const float4*)&Told[b4];
            float4 tn;
            tn.x = 2.0f * acc[r][h * 4 + 0] - 2.0f * tc.x - to.x;
            tn.y = 2.0f * acc[r][h * 4 + 1] - 2.0f * tc.y - to.y;
            tn.z = 2.0f * acc[r][h * 4 + 2] - 2.0f * tc.z - to.z;
            tn.w = 2.0f * acc[r][h * 4 + 3] - 2.0f * tc.w - to.w;
            *(float4*)&Tnew[b4] = tn;
#pragma unroll
            for (int f = 0; f < NF; f++) {
                float4 o = *(const float4*)&out[f * NN + b4];
                o.x = fmaf(cf[f], tn.x, o.x);
                o.y = fmaf(cf[f], tn.y, o.y);
                o.z = fmaf(cf[f], tn.z, o.z);
                o.w = fmaf(cf[f], tn.w, o.w);
                *(float4*)&out[f * NN + b4] = o;
            }
        }
    }
}

// ---------------------------------------------------------------------------
extern "C" void kernel_launch(void* const* d_in, const int* in_sizes, int n_in,
                              void* d_out, int out_size)
{
    const float* L = (const float*)d_in[0];
    float* out = (float*)d_out;

    coef_kernel<<<1, 160>>>();
    init_kernel<<<NN / 256, 256>>>(L, out);

    dim3 grid(N / BN, N / BM);
    int rot = 0;
    for (int k = 2; k <= MORD; k++) {
        cheb_step_kernel<<<grid, 256>>>(L, out, rot, k);
        rot = (rot + 1) % 3;
    }
}

// round 3
// speedup vs baseline: 4.7487x; 4.7487x over previous
#include <cuda_runtime.h>
#include <cuda_bf16.h>
#include <cstdint>

#define NV 4096
#define NNq 16777216ULL          // NV*NV
#define NF 4
#define KMAX 14                  // truncation (tail < 1e-8 relative)
#define NCOEF 33

#define BM 128
#define BN 128
#define BK 32
#define NCHUNK (NV / BK)         // 128
#define LDK 40                   // BK + 8 pad -> 80B row stride, conflict-free
#define TERM_ELEMS (128 * LDK)   // 5120 bf16
#define HALF_ELEMS (2 * TERM_ELEMS)      // A (hi+lo) block
#define BUF_ELEMS  (4 * TERM_ELEMS)      // A hi/lo + B hi/lo
#define BUF_BYTES  (BUF_ELEMS * 2)       // 40960
#define NSTAGE 3
#define SMEM_BYTES (NSTAGE * BUF_BYTES)  // 122880

// ---------------------------------------------------------------------------
// Static device scratch
// ---------------------------------------------------------------------------
__device__ float g_T[(KMAX + 1) * NNq];       // T_0..T_14 fp32
__device__ __nv_bfloat16 g_Bh[2][NNq];        // bf16 hi split of T (ping-pong)
__device__ __nv_bfloat16 g_Bl[2][NNq];        // bf16 lo split of T
__device__ __nv_bfloat16 g_Ah[NNq];           // bf16 hi split of L
__device__ __nv_bfloat16 g_Al[NNq];           // bf16 lo split of L
__device__ float g_coef[NCOEF * NF];

// ---------------------------------------------------------------------------
// Helpers
// ---------------------------------------------------------------------------
__device__ __forceinline__ uint32_t s2u(const void* p) {
    uint32_t a;
    asm("{ .reg .u64 t; cvta.to.shared.u64 t, %1; cvt.u32.u64 %0, t; }"
        : "=r"(a) : "l"(p));
    return a;
}

__device__ __forceinline__ void cp16(uint32_t dst, const void* src) {
    asm volatile("cp.async.cg.shared.global [%0], [%1], 16;" :: "r"(dst), "l"(src));
}
#define CP_COMMIT() asm volatile("cp.async.commit_group;" ::: "memory")
#define CP_WAIT1()  asm volatile("cp.async.wait_group 1;" ::: "memory")

__device__ __forceinline__ void ldm_x4(uint32_t* r, uint32_t addr) {
    asm volatile("ldmatrix.sync.aligned.m8n8.x4.shared.b16 {%0,%1,%2,%3}, [%4];"
                 : "=r"(r[0]), "=r"(r[1]), "=r"(r[2]), "=r"(r[3]) : "r"(addr));
}

__device__ __forceinline__ void mma_bf16(float* d, const uint32_t* a,
                                         uint32_t b0, uint32_t b1) {
    asm volatile(
        "mma.sync.aligned.m16n8k16.row.col.f32.bf16.bf16.f32 "
        "{%0,%1,%2,%3}, {%4,%5,%6,%7}, {%8,%9}, {%0,%1,%2,%3};"
        : "+f"(d[0]), "+f"(d[1]), "+f"(d[2]), "+f"(d[3])
        : "r"(a[0]), "r"(a[1]), "r"(a[2]), "r"(a[3]), "r"(b0), "r"(b1));
}

// ---------------------------------------------------------------------------
// Chebyshev coefficients (fp64); sqrt(N)=64 and 0.5*c0 folded in
// ---------------------------------------------------------------------------
__global__ void coef_kernel() {
    int t = threadIdx.x;
    if (t >= NCOEF * NF) return;
    int o = t >> 2, f = t & 3;
    const double taus[4] = {0.5, 1.0, 2.0, 4.0};
    const double PI = 3.14159265358979323846;
    double s = 0.0;
    for (int j = 0; j < NCOEF; j++) {
        double u = (j + 0.5) / (double)NCOEF;
        double x = cos(PI * u) + 1.0;
        s += cos(PI * (double)o * u) * exp(-taus[f] * x);
    }
    double c = (2.0 / (double)NCOEF) * s * 64.0;
    if (o == 0) c *= 0.5;
    g_coef[o * NF + f] = (float)c;
}

// ---------------------------------------------------------------------------
// Prep: T0 = I, T1 = L - I; bf16 hi/lo splits of L and T1
// ---------------------------------------------------------------------------
__global__ void prep_kernel(const float* __restrict__ L) {
    size_t idx = (size_t)blockIdx.x * 256 + threadIdx.x;
    int i = (int)(idx >> 12), j = (int)(idx & (NV - 1));
    float l = L[idx];
    float d = (i == j) ? 1.0f : 0.0f;
    float t1 = l - d;
    g_T[idx] = d;
    g_T[NNq + idx] = t1;
    __nv_bfloat16 ah = __float2bfloat16(l);
    g_Ah[idx] = ah;
    g_Al[idx] = __float2bfloat16(l - __bfloat162float(ah));
    __nv_bfloat16 bh = __float2bfloat16(t1);
    g_Bh[1][idx] = bh;
    g_Bl[1][idx] = __float2bfloat16(t1 - __bfloat162float(bh));
}

// ---------------------------------------------------------------------------
// Stage one K-chunk into smem buffer `buf`
// regions: 0 = Ah, 1 = Al, 2 = Bh(rows of T, used as B^T), 3 = Bl
// ---------------------------------------------------------------------------
__device__ __forceinline__ void load_chunk(
    uint32_t sb, int buf, int c, int i0, int j0, int tid,
    const __nv_bfloat16* __restrict__ Bh_in,
    const __nv_bfloat16* __restrict__ Bl_in)
{
    const int k0 = c * BK;
    const uint32_t base = sb + buf * BUF_BYTES;
#pragma unroll
    for (int it = 0; it < 8; ++it) {
        int u = tid + it * 256;              // 0..2047
        int reg = u >> 9;                    // 0..3
        int v = u & 511;
        int row = v >> 2, q = v & 3;
        const __nv_bfloat16* src;
        int grow;
        if (reg == 0)      { src = g_Ah;  grow = i0 + row; }
        else if (reg == 1) { src = g_Al;  grow = i0 + row; }
        else if (reg == 2) { src = Bh_in; grow = j0 + row; }
        else               { src = Bl_in; grow = j0 + row; }
        uint32_t off = ((reg >> 1) * HALF_ELEMS + (reg & 1) * TERM_ELEMS
                        + row * LDK + q * 8) * 2;
        cp16(base + off, src + (size_t)grow * NV + k0 + q * 8);
    }
}

// ---------------------------------------------------------------------------
// One Chebyshev step: acc = L @ T_{k-1} (3-term bf16 split HMMA), epilogue
// T_k = 2*acc - 2*T_{k-1} - T_{k-2}, plus bf16 hi/lo split of T_k.
// ---------------------------------------------------------------------------
__global__ void __launch_bounds__(256, 1)
cheb_mma_kernel(int k)
{
    extern __shared__ __align__(16) char smem[];
    const uint32_t sb = s2u(smem);
    const int tid = threadIdx.x;
    const int wid = tid >> 5;
    const int lane = tid & 31;
    const int warp_m = wid & 3;          // 4 warps over M (32 rows each)
    const int warp_n = wid >> 2;         // 2 warps over N (64 cols each)
    const int i0 = blockIdx.y * BM;
    const int j0 = blockIdx.x * BN;

    const float* __restrict__ Tcur = g_T + (size_t)(k - 1) * NNq;
    const float* __restrict__ Told = g_T + (size_t)(k - 2) * NNq;
    float* __restrict__ Tnew = g_T + (size_t)k * NNq;
    const __nv_bfloat16* __restrict__ Bh_in = g_Bh[(k - 1) & 1];
    const __nv_bfloat16* __restrict__ Bl_in = g_Bl[(k - 1) & 1];
    __nv_bfloat16* __restrict__ Bh_out = g_Bh[k & 1];
    __nv_bfloat16* __restrict__ Bl_out = g_Bl[k & 1];

    float acc[2][8][4];
#pragma unroll
    for (int a = 0; a < 2; ++a)
#pragma unroll
        for (int b = 0; b < 8; ++b)
#pragma unroll
            for (int d = 0; d < 4; ++d) acc[a][b][d] = 0.0f;

    // prologue: stage chunks 0 and 1
    load_chunk(sb, 0, 0, i0, j0, tid, Bh_in, Bl_in); CP_COMMIT();
    load_chunk(sb, 1, 1, i0, j0, tid, Bh_in, Bl_in); CP_COMMIT();

    for (int c = 0; c < NCHUNK; ++c) {
        CP_WAIT1();                         // chunk c resident
        __syncthreads();
        if (c + 2 < NCHUNK)
            load_chunk(sb, (c + 2) % NSTAGE, c + 2, i0, j0, tid, Bh_in, Bl_in);
        CP_COMMIT();                        // (possibly empty) keeps group count

        const uint32_t aBase = sb + (c % NSTAGE) * BUF_BYTES;
        const uint32_t bBase = aBase + HALF_ELEMS * 2;

#pragma unroll
        for (int s = 0; s < 2; ++s) {       // two k16 steps per BK=32 chunk
            uint32_t ah[2][4], al[2][4], bh[4][4], bl[4][4];
#pragma unroll
            for (int mt = 0; mt < 2; ++mt) {
                const int row = warp_m * 32 + mt * 16 + (lane & 15);
                const int col = s * 16 + (lane >> 4) * 8;
                const uint32_t addr = aBase + (row * LDK + col) * 2;
                ldm_x4(ah[mt], addr);
                ldm_x4(al[mt], addr + TERM_ELEMS * 2);
            }
#pragma unroll
            for (int p = 0; p < 4; ++p) {
                const int n = warp_n * 64 + p * 16 + (lane & 7) + ((lane >> 4) & 1) * 8;
                const int kk = s * 16 + ((lane >> 3) & 1) * 8;
                const uint32_t addr = bBase + (n * LDK + kk) * 2;
                ldm_x4(bh[p], addr);
                ldm_x4(bl[p], addr + TERM_ELEMS * 2);
            }
#pragma unroll
            for (int mt = 0; mt < 2; ++mt)
#pragma unroll
                for (int p = 0; p < 4; ++p) {
                    mma_bf16(acc[mt][2 * p + 0], ah[mt], bh[p][0], bh[p][1]);
                    mma_bf16(acc[mt][2 * p + 1], ah[mt], bh[p][2], bh[p][3]);
                    mma_bf16(acc[mt][2 * p + 0], ah[mt], bl[p][0], bl[p][1]);
                    mma_bf16(acc[mt][2 * p + 1], ah[mt], bl[p][2], bl[p][3]);
                    mma_bf16(acc[mt][2 * p + 0], al[mt], bh[p][0], bh[p][1]);
                    mma_bf16(acc[mt][2 * p + 1], al[mt], bh[p][2], bh[p][3]);
                }
        }
        __syncthreads();
    }

    // ---- epilogue: Tnew = 2*acc - 2*Tcur - Told, bf16 split out
#pragma unroll
    for (int mt = 0; mt < 2; ++mt)
#pragma unroll
        for (int nt = 0; nt < 8; ++nt) {
            const int r0 = i0 + warp_m * 32 + mt * 16 + (lane >> 2);
            const int c0 = j0 + warp_n * 64 + nt * 8 + (lane & 3) * 2;
#pragma unroll
            for (int half = 0; half < 2; ++half) {
                const int r = r0 + half * 8;
                const size_t idx = (size_t)r * NV + c0;
                const float ax = acc[mt][nt][half * 2 + 0];
                const float ay = acc[mt][nt][half * 2 + 1];
                float2 tc = *(const float2*)(Tcur + idx);
                float2 to = *(const float2*)(Told + idx);
                float2 tn;
                tn.x = 2.0f * ax - 2.0f * tc.x - to.x;
                tn.y = 2.0f * ay - 2.0f * tc.y - to.y;
                *(float2*)(Tnew + idx) = tn;
                __nv_bfloat162 H, Lo;
                H.x = __float2bfloat16(tn.x);
                H.y = __float2bfloat16(tn.y);
                Lo.x = __float2bfloat16(tn.x - __bfloat162float(H.x));
                Lo.y = __float2bfloat16(tn.y - __bfloat162float(H.y));
                *(uint32_t*)(Bh_out + idx) = *reinterpret_cast<uint32_t*>(&H);
                *(uint32_t*)(Bl_out + idx) = *reinterpret_cast<uint32_t*>(&Lo);
            }
        }
}

// ---------------------------------------------------------------------------
// Final reduction: out[f] = c0[f]*I + sum_{k=1..KMAX} c_k[f] * T_k
// ---------------------------------------------------------------------------
__global__ void reduce_kernel(float* __restrict__ out) {
    size_t e = (size_t)blockIdx.x * 256 + threadIdx.x;
    size_t base = e * 4;
    int i = (int)(base >> 12);
    int jb = (int)(base & (NV - 1));
    float4 acc[NF];
#pragma unroll
    for (int f = 0; f < NF; ++f) {
        float c0 = g_coef[f];
        acc[f].x = (i == jb + 0) ? c0 : 0.0f;
        acc[f].y = (i == jb + 1) ? c0 : 0.0f;
        acc[f].z = (i == jb + 2) ? c0 : 0.0f;
        acc[f].w = (i == jb + 3) ? c0 : 0.0f;
    }
    for (int k = 1; k <= KMAX; ++k) {
        float4 t = *(const float4*)(g_T + (size_t)k * NNq + base);
#pragma unroll
        for (int f = 0; f < NF; ++f) {
            float c = g_coef[k * NF + f];
            acc[f].x = fmaf(c, t.x, acc[f].x);
            acc[f].y = fmaf(c, t.y, acc[f].y);
            acc[f].z = fmaf(c, t.z, acc[f].z);
            acc[f].w = fmaf(c, t.w, acc[f].w);
        }
    }
#pragma unroll
    for (int f = 0; f < NF; ++f)
        *(float4*)(out + (size_t)f * NNq + base) = acc[f];
}

// ---------------------------------------------------------------------------
extern "C" void kernel_launch(void* const* d_in, const int* in_sizes, int n_in,
                              void* d_out, int out_size)
{
    const float* L = (const float*)d_in[0];
    float* out = (float*)d_out;

    cudaFuncSetAttribute(cheb_mma_kernel,
                         cudaFuncAttributeMaxDynamicSharedMemorySize, SMEM_BYTES);

    coef_kernel<<<1, 160>>>();
    prep_kernel<<<(int)(NNq / 256), 256>>>(L);

    dim3 grid(NV / BN, NV / BM);   // 32 x 32
    for (int k = 2; k <= KMAX; ++k)
        cheb_mma_kernel<<<grid, 256, SMEM_BYTES>>>(k);

    reduce_kernel<<<(int)(NNq / 4 / 256), 256>>>(out);
}

// round 4
// speedup vs baseline: 5.8718x; 1.2365x over previous
#include <cuda_runtime.h>
#include <cuda_bf16.h>
#include <cstdint>

#define NV 4096
#define NNq 16777216ULL          // NV*NV
#define NF 4
#define KMAX 14                  // truncation (tail < 1e-8 relative)
#define NCOEF 33

#define BM 128
#define BN 128
#define BK 32
#define NCHUNK (NV / BK)         // 128
#define LDK 40                   // BK + 8 pad -> 80B row stride, conflict-free
#define TERM_ELEMS (128 * LDK)   // 5120 bf16
#define HALF_ELEMS (2 * TERM_ELEMS)      // A (hi+lo) block
#define BUF_ELEMS  (4 * TERM_ELEMS)      // A hi/lo + B hi/lo
#define BUF_BYTES  (BUF_ELEMS * 2)       // 40960
#define NSTAGE 2
#define SMEM_BYTES (NSTAGE * BUF_BYTES)  // 81920 -> 2 CTAs/SM

// ---------------------------------------------------------------------------
// Static device scratch
// ---------------------------------------------------------------------------
__device__ float g_T[(KMAX + 1) * NNq];       // T_0..T_14 fp32
__device__ __nv_bfloat16 g_Bh[2][NNq];        // bf16 hi split of T (ping-pong)
__device__ __nv_bfloat16 g_Bl[2][NNq];        // bf16 lo split of T
__device__ __nv_bfloat16 g_Ah[NNq];           // bf16 hi split of L
__device__ __nv_bfloat16 g_Al[NNq];           // bf16 lo split of L
__device__ float g_coef[NCOEF * NF];

// ---------------------------------------------------------------------------
// Helpers
// ---------------------------------------------------------------------------
__device__ __forceinline__ uint32_t s2u(const void* p) {
    uint32_t a;
    asm("{ .reg .u64 t; cvta.to.shared.u64 t, %1; cvt.u32.u64 %0, t; }"
        : "=r"(a) : "l"(p));
    return a;
}

__device__ __forceinline__ void cp16(uint32_t dst, const void* src) {
    asm volatile("cp.async.cg.shared.global [%0], [%1], 16;" :: "r"(dst), "l"(src));
}
#define CP_COMMIT() asm volatile("cp.async.commit_group;" ::: "memory")
#define CP_WAIT(n)  asm volatile("cp.async.wait_group %0;" :: "n"(n) : "memory")

__device__ __forceinline__ void ldm_x4(uint32_t* r, uint32_t addr) {
    asm volatile("ldmatrix.sync.aligned.m8n8.x4.shared.b16 {%0,%1,%2,%3}, [%4];"
                 : "=r"(r[0]), "=r"(r[1]), "=r"(r[2]), "=r"(r[3]) : "r"(addr));
}

__device__ __forceinline__ void mma_bf16(float* d, const uint32_t* a,
                                         uint32_t b0, uint32_t b1) {
    asm volatile(
        "mma.sync.aligned.m16n8k16.row.col.f32.bf16.bf16.f32 "
        "{%0,%1,%2,%3}, {%4,%5,%6,%7}, {%8,%9}, {%0,%1,%2,%3};"
        : "+f"(d[0]), "+f"(d[1]), "+f"(d[2]), "+f"(d[3])
        : "r"(a[0]), "r"(a[1]), "r"(a[2]), "r"(a[3]), "r"(b0), "r"(b1));
}

// ---------------------------------------------------------------------------
// Chebyshev coefficients (fp64); sqrt(N)=64 and 0.5*c0 folded in
// ---------------------------------------------------------------------------
__global__ void coef_kernel() {
    int t = threadIdx.x;
    if (t >= NCOEF * NF) return;
    int o = t >> 2, f = t & 3;
    const double taus[4] = {0.5, 1.0, 2.0, 4.0};
    const double PI = 3.14159265358979323846;
    double s = 0.0;
    for (int j = 0; j < NCOEF; j++) {
        double u = (j + 0.5) / (double)NCOEF;
        double x = cos(PI * u) + 1.0;
        s += cos(PI * (double)o * u) * exp(-taus[f] * x);
    }
    double c = (2.0 / (double)NCOEF) * s * 64.0;
    if (o == 0) c *= 0.5;
    g_coef[o * NF + f] = (float)c;
}

// ---------------------------------------------------------------------------
// Prep: T0 = I, T1 = L - I; bf16 hi/lo splits of L and T1
// ---------------------------------------------------------------------------
__global__ void prep_kernel(const float* __restrict__ L) {
    size_t idx = (size_t)blockIdx.x * 256 + threadIdx.x;
    int i = (int)(idx >> 12), j = (int)(idx & (NV - 1));
    float l = L[idx];
    float d = (i == j) ? 1.0f : 0.0f;
    float t1 = l - d;
    g_T[idx] = d;
    g_T[NNq + idx] = t1;
    __nv_bfloat16 ah = __float2bfloat16(l);
    g_Ah[idx] = ah;
    g_Al[idx] = __float2bfloat16(l - __bfloat162float(ah));
    __nv_bfloat16 bh = __float2bfloat16(t1);
    g_Bh[1][idx] = bh;
    g_Bl[1][idx] = __float2bfloat16(t1 - __bfloat162float(bh));
}

// ---------------------------------------------------------------------------
// Stage one K-chunk into smem buffer `buf`
// regions: 0 = Ah, 1 = Al, 2 = Bh (rows of T, used as B^T), 3 = Bl
// ---------------------------------------------------------------------------
__device__ __forceinline__ void load_chunk(
    uint32_t sb, int buf, int c, int i0, int j0, int tid,
    const __nv_bfloat16* __restrict__ Bh_in,
    const __nv_bfloat16* __restrict__ Bl_in)
{
    const int k0 = c * BK;
    const uint32_t base = sb + buf * BUF_BYTES;
#pragma unroll
    for (int it = 0; it < 8; ++it) {
        int u = tid + it * 256;              // 0..2047
        int reg = u >> 9;                    // 0..3
        int v = u & 511;
        int row = v >> 2, q = v & 3;
        const __nv_bfloat16* src;
        int grow;
        if (reg == 0)      { src = g_Ah;  grow = i0 + row; }
        else if (reg == 1) { src = g_Al;  grow = i0 + row; }
        else if (reg == 2) { src = Bh_in; grow = j0 + row; }
        else               { src = Bl_in; grow = j0 + row; }
        uint32_t off = ((reg >> 1) * HALF_ELEMS + (reg & 1) * TERM_ELEMS
                        + row * LDK + q * 8) * 2;
        cp16(base + off, src + (size_t)grow * NV + k0 + q * 8);
    }
}

// ---------------------------------------------------------------------------
// One Chebyshev step: acc = L @ T_{k-1} (3-term bf16 split HMMA), epilogue
// T_k = 2*acc - 2*T_{k-1} - T_{k-2}, plus bf16 hi/lo split of T_k.
// 2-stage pipeline, 2 CTAs/SM.
// ---------------------------------------------------------------------------
__global__ void __launch_bounds__(256, 2)
cheb_mma_kernel(int k)
{
    extern __shared__ __align__(16) char smem[];
    const uint32_t sb = s2u(smem);
    const int tid = threadIdx.x;
    const int wid = tid >> 5;
    const int lane = tid & 31;
    const int warp_m = wid & 3;          // 4 warps over M (32 rows each)
    const int warp_n = wid >> 2;         // 2 warps over N (64 cols each)
    const int i0 = blockIdx.y * BM;
    const int j0 = blockIdx.x * BN;

    const float* __restrict__ Tcur = g_T + (size_t)(k - 1) * NNq;
    const float* __restrict__ Told = g_T + (size_t)(k - 2) * NNq;
    float* __restrict__ Tnew = g_T + (size_t)k * NNq;
    const __nv_bfloat16* __restrict__ Bh_in = g_Bh[(k - 1) & 1];
    const __nv_bfloat16* __restrict__ Bl_in = g_Bl[(k - 1) & 1];
    __nv_bfloat16* __restrict__ Bh_out = g_Bh[k & 1];
    __nv_bfloat16* __restrict__ Bl_out = g_Bl[k & 1];

    float acc[2][8][4];
#pragma unroll
    for (int a = 0; a < 2; ++a)
#pragma unroll
        for (int b = 0; b < 8; ++b)
#pragma unroll
            for (int d = 0; d < 4; ++d) acc[a][b][d] = 0.0f;

    // prologue: stage chunk 0
    load_chunk(sb, 0, 0, i0, j0, tid, Bh_in, Bl_in); CP_COMMIT();

    for (int c = 0; c < NCHUNK; ++c) {
        if (c + 1 < NCHUNK) {
            load_chunk(sb, (c + 1) & 1, c + 1, i0, j0, tid, Bh_in, Bl_in);
            CP_COMMIT();
            CP_WAIT(1);                     // chunk c resident
        } else {
            CP_WAIT(0);
        }
        __syncthreads();

        const uint32_t aBase = sb + (c & 1) * BUF_BYTES;
        const uint32_t bBase = aBase + HALF_ELEMS * 2;

#pragma unroll
        for (int s = 0; s < 2; ++s) {       // two k16 steps per BK=32 chunk
            uint32_t ah[2][4], al[2][4];
#pragma unroll
            for (int mt = 0; mt < 2; ++mt) {
                const int row = warp_m * 32 + mt * 16 + (lane & 15);
                const int col = s * 16 + (lane >> 4) * 8;
                const uint32_t addr = aBase + (row * LDK + col) * 2;
                ldm_x4(ah[mt], addr);
                ldm_x4(al[mt], addr + TERM_ELEMS * 2);
            }
#pragma unroll
            for (int pp = 0; pp < 2; ++pp) {   // process B in pairs of n16 tiles
                uint32_t bh[2][4], bl[2][4];
#pragma unroll
                for (int p2 = 0; p2 < 2; ++p2) {
                    const int p = pp * 2 + p2;
                    const int n = warp_n * 64 + p * 16 + (lane & 7) + ((lane >> 4) & 1) * 8;
                    const int kk = s * 16 + ((lane >> 3) & 1) * 8;
                    const uint32_t addr = bBase + (n * LDK + kk) * 2;
                    ldm_x4(bh[p2], addr);
                    ldm_x4(bl[p2], addr + TERM_ELEMS * 2);
                }
#pragma unroll
                for (int mt = 0; mt < 2; ++mt)
#pragma unroll
                    for (int p2 = 0; p2 < 2; ++p2) {
                        const int nt = 2 * (pp * 2 + p2);
                        mma_bf16(acc[mt][nt + 0], ah[mt], bh[p2][0], bh[p2][1]);
                        mma_bf16(acc[mt][nt + 1], ah[mt], bh[p2][2], bh[p2][3]);
                        mma_bf16(acc[mt][nt + 0], ah[mt], bl[p2][0], bl[p2][1]);
                        mma_bf16(acc[mt][nt + 1], ah[mt], bl[p2][2], bl[p2][3]);
                        mma_bf16(acc[mt][nt + 0], al[mt], bh[p2][0], bh[p2][1]);
                        mma_bf16(acc[mt][nt + 1], al[mt], bh[p2][2], bh[p2][3]);
                    }
            }
        }
        __syncthreads();
    }

    // ---- epilogue: Tnew = 2*acc - 2*Tcur - Told, bf16 split out
#pragma unroll
    for (int mt = 0; mt < 2; ++mt)
#pragma unroll
        for (int nt = 0; nt < 8; ++nt) {
            const int r0 = i0 + warp_m * 32 + mt * 16 + (lane >> 2);
            const int c0 = j0 + warp_n * 64 + nt * 8 + (lane & 3) * 2;
#pragma unroll
            for (int half = 0; half < 2; ++half) {
                const int r = r0 + half * 8;
                const size_t idx = (size_t)r * NV + c0;
                const float ax = acc[mt][nt][half * 2 + 0];
                const float ay = acc[mt][nt][half * 2 + 1];
                float2 tc = *(const float2*)(Tcur + idx);
                float2 to = *(const float2*)(Told + idx);
                float2 tn;
                tn.x = 2.0f * ax - 2.0f * tc.x - to.x;
                tn.y = 2.0f * ay - 2.0f * tc.y - to.y;
                *(float2*)(Tnew + idx) = tn;
                __nv_bfloat162 H, Lo;
                H.x = __float2bfloat16(tn.x);
                H.y = __float2bfloat16(tn.y);
                Lo.x = __float2bfloat16(tn.x - __bfloat162float(H.x));
                Lo.y = __float2bfloat16(tn.y - __bfloat162float(H.y));
                *(uint32_t*)(Bh_out + idx) = *reinterpret_cast<uint32_t*>(&H);
                *(uint32_t*)(Bl_out + idx) = *reinterpret_cast<uint32_t*>(&Lo);
            }
        }
}

// ---------------------------------------------------------------------------
// Final reduction: out[f] = c0[f]*I + sum_{k=1..KMAX} c_k[f] * T_k
// ---------------------------------------------------------------------------
__global__ void reduce_kernel(float* __restrict__ out) {
    size_t e = (size_t)blockIdx.x * 256 + threadIdx.x;
    size_t base = e * 4;
    int i = (int)(base >> 12);
    int jb = (int)(base & (NV - 1));
    float4 acc[NF];
#pragma unroll
    for (int f = 0; f < NF; ++f) {
        float c0 = g_coef[f];
        acc[f].x = (i == jb + 0) ? c0 : 0.0f;
        acc[f].y = (i == jb + 1) ? c0 : 0.0f;
        acc[f].z = (i == jb + 2) ? c0 : 0.0f;
        acc[f].w = (i == jb + 3) ? c0 : 0.0f;
    }
    for (int k = 1; k <= KMAX; ++k) {
        float4 t = *(const float4*)(g_T + (size_t)k * NNq + base);
#pragma unroll
        for (int f = 0; f < NF; ++f) {
            float c = g_coef[k * NF + f];
            acc[f].x = fmaf(c, t.x, acc[f].x);
            acc[f].y = fmaf(c, t.y, acc[f].y);
            acc[f].z = fmaf(c, t.z, acc[f].z);
            acc[f].w = fmaf(c, t.w, acc[f].w);
        }
    }
#pragma unroll
    for (int f = 0; f < NF; ++f)
        *(float4*)(out + (size_t)f * NNq + base) = acc[f];
}

// ---------------------------------------------------------------------------
extern "C" void kernel_launch(void* const* d_in, const int* in_sizes, int n_in,
                              void* d_out, int out_size)
{
    const float* L = (const float*)d_in[0];
    float* out = (float*)d_out;

    cudaFuncSetAttribute(cheb_mma_kernel,
                         cudaFuncAttributeMaxDynamicSharedMemorySize, SMEM_BYTES);

    coef_kernel<<<1, 160>>>();
    prep_kernel<<<(int)(NNq / 256), 256>>>(L);

    dim3 grid(NV / BN, NV / BM);   // 32 x 32
    for (int k = 2; k <= KMAX; ++k)
        cheb_mma_kernel<<<grid, 256, SMEM_BYTES>>>(k);

    reduce_kernel<<<(int)(NNq / 4 / 256), 256>>>(out);
}

// round 6
// speedup vs baseline: 9.4361x; 1.6070x over previous
#include <cuda_runtime.h>
#include <cuda_bf16.h>
#include <cstdint>

#define NV 4096
#define NNq 16777216ULL          // NV*NV
#define NF 4
#define KMAX 10                  // truncation (tail ~8e-6 of the tau=4 filter)
#define NCOEF 33

#define BM 128
#define BN 128
#define BK 32
#define NCHUNK (NV / BK)         // 128
#define REGION_BYTES 8192        // 128 rows x 64B (swizzled, no pad)
#define BUF_BYTES (4 * REGION_BYTES)   // Ah, Al, Bh, Bl = 32768
#define NSTAGE 3
#define SMEM_BYTES (NSTAGE * BUF_BYTES)  // 98304 -> 2 CTAs/SM (192KB/SM)

// 64B-row swizzle: bits[5:4] ^= bits[8:7]; conflict-free ldmatrix at 64B stride
#define SWZ64(x) ((x) ^ (((x) >> 3) & 0x30))

// ---------------------------------------------------------------------------
// Static device scratch
// ---------------------------------------------------------------------------
__device__ float g_T[(KMAX + 1) * NNq];       // T_0..T_KMAX fp32
__device__ __nv_bfloat16 g_Bh[2][NNq];        // bf16 hi split of T (ping-pong)
__device__ __nv_bfloat16 g_Bl[2][NNq];        // bf16 lo split of T
__device__ __nv_bfloat16 g_Ah[NNq];           // bf16 hi split of L
__device__ __nv_bfloat16 g_Al[NNq];           // bf16 lo split of L
__device__ float g_coef[NCOEF * NF];

// ---------------------------------------------------------------------------
// Helpers
// ---------------------------------------------------------------------------
__device__ __forceinline__ uint32_t s2u(const void* p) {
    uint32_t a;
    asm("{ .reg .u64 t; cvta.to.shared.u64 t, %1; cvt.u32.u64 %0, t; }"
        : "=r"(a) : "l"(p));
    return a;
}

__device__ __forceinline__ void cp16(uint32_t dst, const void* src) {
    asm volatile("cp.async.cg.shared.global [%0], [%1], 16;" :: "r"(dst), "l"(src));
}
#define CP_COMMIT() asm volatile("cp.async.commit_group;" ::: "memory")
#define CP_WAIT(n)  asm volatile("cp.async.wait_group %0;" :: "n"(n) : "memory")

__device__ __forceinline__ void ldm_x4(uint32_t* r, uint32_t addr) {
    asm volatile("ldmatrix.sync.aligned.m8n8.x4.shared.b16 {%0,%1,%2,%3}, [%4];"
                 : "=r"(r[0]), "=r"(r[1]), "=r"(r[2]), "=r"(r[3]) : "r"(addr));
}

__device__ __forceinline__ void mma_bf16(float* d, const uint32_t* a,
                                         uint32_t b0, uint32_t b1) {
    asm volatile(
        "mma.sync.aligned.m16n8k16.row.col.f32.bf16.bf16.f32 "
        "{%0,%1,%2,%3}, {%4,%5,%6,%7}, {%8,%9}, {%0,%1,%2,%3};"
        : "+f"(d[0]), "+f"(d[1]), "+f"(d[2]), "+f"(d[3])
        : "r"(a[0]), "r"(a[1]), "r"(a[2]), "r"(a[3]), "r"(b0), "r"(b1));
}

// ---------------------------------------------------------------------------
// Chebyshev coefficients (fp64); sqrt(N)=64 and 0.5*c0 folded in
// ---------------------------------------------------------------------------
__global__ void coef_kernel() {
    int t = threadIdx.x;
    if (t >= NCOEF * NF) return;
    int o = t >> 2, f = t & 3;
    const double taus[4] = {0.5, 1.0, 2.0, 4.0};
    const double PI = 3.14159265358979323846;
    double s = 0.0;
    for (int j = 0; j < NCOEF; j++) {
        double u = (j + 0.5) / (double)NCOEF;
        double x = cos(PI * u) + 1.0;
        s += cos(PI * (double)o * u) * exp(-taus[f] * x);
    }
    double c = (2.0 / (double)NCOEF) * s * 64.0;
    if (o == 0) c *= 0.5;
    g_coef[o * NF + f] = (float)c;
}

// ---------------------------------------------------------------------------
// Prep: T0 = I, T1 = L - I; bf16 hi/lo splits of L and T1
// ---------------------------------------------------------------------------
__global__ void prep_kernel(const float* __restrict__ L) {
    size_t idx = (size_t)blockIdx.x * 256 + threadIdx.x;
    int i = (int)(idx >> 12), j = (int)(idx & (NV - 1));
    float l = L[idx];
    float d = (i == j) ? 1.0f : 0.0f;
    float t1 = l - d;
    g_T[idx] = d;
    g_T[NNq + idx] = t1;
    __nv_bfloat16 ah = __float2bfloat16(l);
    g_Ah[idx] = ah;
    g_Al[idx] = __float2bfloat16(l - __bfloat162float(ah));
    __nv_bfloat16 bh = __float2bfloat16(t1);
    g_Bh[1][idx] = bh;
    g_Bl[1][idx] = __float2bfloat16(t1 - __bfloat162float(bh));
}

// ---------------------------------------------------------------------------
// Stage one K-chunk: regions 0=Ah, 1=Al, 2=Bh (rows of T = B^T), 3=Bl
// ---------------------------------------------------------------------------
__device__ __forceinline__ void load_chunk(
    uint32_t sb, int buf, int c, int i0, int j0, int tid,
    const __nv_bfloat16* __restrict__ Bh_in,
    const __nv_bfloat16* __restrict__ Bl_in)
{
    const int k0 = c * BK;
    const uint32_t base = sb + buf * BUF_BYTES;
#pragma unroll
    for (int it = 0; it < 8; ++it) {
        int u = tid + it * 256;              // 0..2047
        int reg = u >> 9;                    // 0..3
        int v = u & 511;
        int row = v >> 2, q = v & 3;
        const __nv_bfloat16* src;
        int grow;
        if (reg == 0)      { src = g_Ah;  grow = i0 + row; }
        else if (reg == 1) { src = g_Al;  grow = i0 + row; }
        else if (reg == 2) { src = Bh_in; grow = j0 + row; }
        else               { src = Bl_in; grow = j0 + row; }
        uint32_t off = reg * REGION_BYTES + SWZ64((uint32_t)(row * 64 + q * 16));
        cp16(base + off, src + (size_t)grow * NV + k0 + q * 8);
    }
}

// ---------------------------------------------------------------------------
// One Chebyshev step: acc = L @ T_{k-1} (3-term bf16 split HMMA), epilogue
// T_k = 2*acc - 2*T_{k-1} - T_{k-2}, plus bf16 hi/lo split of T_k.
// 3-stage pipeline, one barrier per chunk, 2 CTAs/SM.
// ---------------------------------------------------------------------------
__global__ void __launch_bounds__(256, 2)
cheb_mma_kernel(int k)
{
    extern __shared__ __align__(16) char smem[];
    const uint32_t sb = s2u(smem);
    const int tid = threadIdx.x;
    const int wid = tid >> 5;
    const int lane = tid & 31;
    const int warp_m = wid & 3;          // 4 warps over M (32 rows each)
    const int warp_n = wid >> 2;         // 2 warps over N (64 cols each)
    const int i0 = blockIdx.y * BM;
    const int j0 = blockIdx.x * BN;

    const float* __restrict__ Tcur = g_T + (size_t)(k - 1) * NNq;
    const float* __restrict__ Told = g_T + (size_t)(k - 2) * NNq;
    float* __restrict__ Tnew = g_T + (size_t)k * NNq;
    const __nv_bfloat16* __restrict__ Bh_in = g_Bh[(k - 1) & 1];
    const __nv_bfloat16* __restrict__ Bl_in = g_Bl[(k - 1) & 1];
    __nv_bfloat16* __restrict__ Bh_out = g_Bh[k & 1];
    __nv_bfloat16* __restrict__ Bl_out = g_Bl[k & 1];

    float acc[2][8][4];
#pragma unroll
    for (int a = 0; a < 2; ++a)
#pragma unroll
        for (int b = 0; b < 8; ++b)
#pragma unroll
            for (int d = 0; d < 4; ++d) acc[a][b][d] = 0.0f;

    // prologue: stage chunks 0 and 1
    load_chunk(sb, 0, 0, i0, j0, tid, Bh_in, Bl_in); CP_COMMIT();
    load_chunk(sb, 1, 1, i0, j0, tid, Bh_in, Bl_in); CP_COMMIT();

    for (int c = 0; c < NCHUNK; ++c) {
        if (c + 1 < NCHUNK) CP_WAIT(1); else CP_WAIT(0);   // chunk c resident
        __syncthreads();   // also: all warps done reading stage (c-1)%3

        if (c + 2 < NCHUNK) {
            load_chunk(sb, (c + 2) % NSTAGE, c + 2, i0, j0, tid, Bh_in, Bl_in);
            CP_COMMIT();
        }

        const uint32_t aBase = sb + (c % NSTAGE) * BUF_BYTES;
        const uint32_t bBase = aBase + 2 * REGION_BYTES;

#pragma unroll
        for (int s = 0; s < 2; ++s) {       // two k16 steps per BK=32 chunk
            uint32_t ah[2][4], al[2][4];
#pragma unroll
            for (int mt = 0; mt < 2; ++mt) {
                const int row = warp_m * 32 + mt * 16 + (lane & 15);
                const int col = s * 16 + (lane >> 4) * 8;
                const uint32_t off = SWZ64((uint32_t)(row * 64 + col * 2));
                ldm_x4(ah[mt], aBase + off);
                ldm_x4(al[mt], aBase + REGION_BYTES + off);
            }
#pragma unroll
            for (int pp = 0; pp < 2; ++pp) {   // B in pairs of n16 tiles
                uint32_t bh[2][4], bl[2][4];
#pragma unroll
                for (int p2 = 0; p2 < 2; ++p2) {
                    const int p = pp * 2 + p2;
                    const int n = warp_n * 64 + p * 16 + (lane & 7) + ((lane >> 4) & 1) * 8;
                    const int kk = s * 16 + ((lane >> 3) & 1) * 8;
                    const uint32_t off = SWZ64((uint32_t)(n * 64 + kk * 2));
                    ldm_x4(bh[p2], bBase + off);
                    ldm_x4(bl[p2], bBase + REGION_BYTES + off);
                }
#pragma unroll
                for (int mt = 0; mt < 2; ++mt)
#pragma unroll
                    for (int p2 = 0; p2 < 2; ++p2) {
                        const int nt = 2 * (pp * 2 + p2);
                        mma_bf16(acc[mt][nt + 0], ah[mt], bh[p2][0], bh[p2][1]);
                        mma_bf16(acc[mt][nt + 1], ah[mt], bh[p2][2], bh[p2][3]);
                        mma_bf16(acc[mt][nt + 0], ah[mt], bl[p2][0], bl[p2][1]);
                        mma_bf16(acc[mt][nt + 1], ah[mt], bl[p2][2], bl[p2][3]);
                        mma_bf16(acc[mt][nt + 0], al[mt], bh[p2][0], bh[p2][1]);
                        mma_bf16(acc[mt][nt + 1], al[mt], bh[p2][2], bh[p2][3]);
                    }
            }
        }
    }

    // ---- epilogue: Tnew = 2*acc - 2*Tcur - Told, bf16 split out
#pragma unroll
    for (int mt = 0; mt < 2; ++mt)
#pragma unroll
        for (int nt = 0; nt < 8; ++nt) {
            const int r0 = i0 + warp_m * 32 + mt * 16 + (lane >> 2);
            const int c0 = j0 + warp_n * 64 + nt * 8 + (lane & 3) * 2;
#pragma unroll
            for (int half = 0; half < 2; ++half) {
                const int r = r0 + half * 8;
                const size_t idx = (size_t)r * NV + c0;
                const float ax = acc[mt][nt][half * 2 + 0];
                const float ay = acc[mt][nt][half * 2 + 1];
                float2 tc = *(const float2*)(Tcur + idx);
                float2 to = *(const float2*)(Told + idx);
                float2 tn;
                tn.x = 2.0f * ax - 2.0f * tc.x - to.x;
                tn.y = 2.0f * ay - 2.0f * tc.y - to.y;
                *(float2*)(Tnew + idx) = tn;
                __nv_bfloat162 H, Lo;
                H.x = __float2bfloat16(tn.x);
                H.y = __float2bfloat16(tn.y);
                Lo.x = __float2bfloat16(tn.x - __bfloat162float(H.x));
                Lo.y = __float2bfloat16(tn.y - __bfloat162float(H.y));
                *(uint32_t*)(Bh_out + idx) = *reinterpret_cast<uint32_t*>(&H);
                *(uint32_t*)(Bl_out + idx) = *reinterpret_cast<uint32_t*>(&Lo);
            }
        }
}

// ---------------------------------------------------------------------------
// Final reduction: out[f] = c0[f]*I + sum_{k=1..KMAX} c_k[f] * T_k
// ---------------------------------------------------------------------------
__global__ void reduce_kernel(float* __restrict__ out) {
    size_t e = (size_t)blockIdx.x * 256 + threadIdx.x;
    size_t base = e * 4;
    int i = (int)(base >> 12);
    int jb = (int)(base & (NV - 1));
    float4 acc[NF];
#pragma unroll
    for (int f = 0; f < NF; ++f) {
        float c0 = g_coef[f];
        acc[f].x = (i == jb + 0) ? c0 : 0.0f;
        acc[f].y = (i == jb + 1) ? c0 : 0.0f;
        acc[f].z = (i == jb + 2) ? c0 : 0.0f;
        acc[f].w = (i == jb + 3) ? c0 : 0.0f;
    }
    for (int k = 1; k <= KMAX; ++k) {
        float4 t = *(const float4*)(g_T + (size_t)k * NNq + base);
#pragma unroll
        for (int f = 0; f < NF; ++f) {
            float c = g_coef[k * NF + f];
            acc[f].x = fmaf(c, t.x, acc[f].x);
            acc[f].y = fmaf(c, t.y, acc[f].y);
            acc[f].z = fmaf(c, t.z, acc[f].z);
            acc[f].w = fmaf(c, t.w, acc[f].w);
        }
    }
#pragma unroll
    for (int f = 0; f < NF; ++f)
        *(float4*)(out + (size_t)f * NNq + base) = acc[f];
}

// ---------------------------------------------------------------------------
extern "C" void kernel_launch(void* const* d_in, const int* in_sizes, int n_in,
                              void* d_out, int out_size)
{
    const float* L = (const float*)d_in[0];
    float* out = (float*)d_out;

    cudaFuncSetAttribute(cheb_mma_kernel,
                         cudaFuncAttributeMaxDynamicSharedMemorySize, SMEM_BYTES);

    coef_kernel<<<1, 160>>>();
    prep_kernel<<<(int)(NNq / 256), 256>>>(L);

    dim3 grid(NV / BN, NV / BM);   // 32 x 32
    for (int k = 2; k <= KMAX; ++k)
        cheb_mma_kernel<<<grid, 256, SMEM_BYTES>>>(k);

    reduce_kernel<<<(int)(NNq / 4 / 256), 256>>>(out);
}